// round 12
// baseline (speedup 1.0000x reference)
#include <cuda_runtime.h>
#include <cuda_bf16.h>
#include <cstdint>

#define NN      50000
#define EE      800000
#define ET      850000
#define HID     128
#define HEADS   4
#define NB      64
#define LAYERS  3
#define LN_EPS  1e-5f
#define NEG_SLOPE 0.2f

#define SCAN_BLK 256
#define NBLK ((NN + SCAN_BLK - 1) / SCAN_BLK)   // 196

// ---------------- device scratch ----------------
__device__ float g_h[NN * HID];
__device__ float g_tmp[NN * HID];
__device__ float g_as[NN * HEADS];
__device__ float g_ad[NN * HEADS];
__device__ int   g_deg[NN];
__device__ int   g_off[NN + 1];
__device__ int   g_cur[NN];
__device__ int   g_bsum[NBLK];
__device__ int   g_csr_src[ET];
__device__ __nv_bfloat16 g_wT_hi[4 * HID * HID];  // [w][n][k] = W[k][n] hi
__device__ __nv_bfloat16 g_wT_lo[4 * HID * HID];

// ---------------- helpers ----------------
__device__ __forceinline__ float warpSum(float v) {
#pragma unroll
    for (int o = 16; o > 0; o >>= 1) v += __shfl_xor_sync(0xffffffffu, v, o);
    return v;
}
__device__ __forceinline__ int warpSumI(int v) {
#pragma unroll
    for (int o = 16; o > 0; o >>= 1) v += __shfl_xor_sync(0xffffffffu, v, o);
    return v;
}
__device__ __forceinline__ int warpScanIncl(int x, int lane) {
#pragma unroll
    for (int o = 1; o < 32; o <<= 1) {
        int t = __shfl_up_sync(0xffffffffu, x, o);
        if (lane >= o) x += t;
    }
    return x;
}
__device__ __forceinline__ float lrelu(float x) { return x > 0.f ? x : NEG_SLOPE * x; }
__device__ __forceinline__ float silu(float x) { return x / (1.f + __expf(-x)); }

__device__ __forceinline__ void mma_bf16(float* c, const uint32_t* a, const uint32_t* b) {
    asm volatile(
        "mma.sync.aligned.m16n8k16.row.col.f32.bf16.bf16.f32 "
        "{%0,%1,%2,%3},{%4,%5,%6,%7},{%8,%9},{%0,%1,%2,%3};"
        : "+f"(c[0]), "+f"(c[1]), "+f"(c[2]), "+f"(c[3])
        : "r"(a[0]), "r"(a[1]), "r"(a[2]), "r"(a[3]), "r"(b[0]), "r"(b[1]));
}

__device__ __forceinline__ void split_pack(float a, float b, uint32_t& h, uint32_t& l) {
    __nv_bfloat16 ha = __float2bfloat16(a), hb = __float2bfloat16(b);
    __nv_bfloat162 hv = __halves2bfloat162(ha, hb);
    __nv_bfloat162 lv = __floats2bfloat162_rn(a - __bfloat162float(ha),
                                              b - __bfloat162float(hb));
    h = *(uint32_t*)&hv;
    l = *(uint32_t*)&lv;
}

// ---------------- weight prep: W^T split into bf16 hi/lo ----------------
__global__ void wprep_kernel(const float* __restrict__ W0, const float* __restrict__ Wg,
                             __nv_bfloat16* __restrict__ bh, __nv_bfloat16* __restrict__ bl) {
    int i = blockIdx.x * blockDim.x + threadIdx.x;
    if (i >= 4 * HID * HID) return;
    int w = i >> 14, rem = i & 16383, n = rem >> 7, k = rem & 127;
    const float* src = (w == 0) ? W0 : (Wg + (w - 1) * HID * HID);
    float v = src[k * HID + n];
    __nv_bfloat16 hi = __float2bfloat16(v);
    bh[i] = hi;
    bl[i] = __float2bfloat16(v - __bfloat162float(hi));
}

// ---------------- CSR build ----------------
__global__ void zero_deg_kernel(int* deg) {
    int i = blockIdx.x * blockDim.x + threadIdx.x;
    if (i < NN) deg[i] = 0;
}
__global__ void count_deg_kernel(const int* __restrict__ ei, int* __restrict__ deg) {
    int i = blockIdx.x * blockDim.x + threadIdx.x;
    if (i >= ET) return;
    int dst = (i < EE) ? ei[EE + i] : (i - EE);
    atomicAdd(&deg[dst], 1);
}
__global__ void scan_part_kernel(const int* __restrict__ deg, int* __restrict__ bsum) {
    __shared__ int sh[SCAN_BLK / 32];
    int tid = threadIdx.x, lane = tid & 31, w = tid >> 5;
    int i = blockIdx.x * SCAN_BLK + tid;
    int v = (i < NN) ? deg[i] : 0;
    int s = warpSumI(v);
    if (lane == 0) sh[w] = s;
    __syncthreads();
    if (w == 0) {
        int t = (lane < SCAN_BLK / 32) ? sh[lane] : 0;
        t = warpSumI(t);
        if (lane == 0) bsum[blockIdx.x] = t;
    }
}
__global__ void scan_top_kernel(int* __restrict__ bsum, int* __restrict__ off) {
    __shared__ int sh[8];
    int tid = threadIdx.x, lane = tid & 31, w = tid >> 5;
    int v = (tid < NBLK) ? bsum[tid] : 0;
    int x = warpScanIncl(v, lane);
    if (lane == 31) sh[w] = x;
    __syncthreads();
    if (w == 0) {
        int t = (lane < 8) ? sh[lane] : 0;
        t = warpScanIncl(t, lane);
        if (lane < 8) sh[lane] = t;
    }
    __syncthreads();
    int incl = x + (w ? sh[w - 1] : 0);
    if (tid < NBLK) bsum[tid] = incl - v;
    if (tid == NBLK - 1) off[NN] = incl;
}
__global__ void scan_add_kernel(const int* __restrict__ deg, const int* __restrict__ bsum,
                                int* __restrict__ off, int* __restrict__ cur) {
    __shared__ int sh[SCAN_BLK / 32];
    int tid = threadIdx.x, lane = tid & 31, w = tid >> 5;
    int i = blockIdx.x * SCAN_BLK + tid;
    int v = (i < NN) ? deg[i] : 0;
    int x = warpScanIncl(v, lane);
    if (lane == 31) sh[w] = x;
    __syncthreads();
    if (w == 0) {
        int t = (lane < SCAN_BLK / 32) ? sh[lane] : 0;
        t = warpScanIncl(t, lane);
        if (lane < SCAN_BLK / 32) sh[lane] = t;
    }
    __syncthreads();
    int excl = x - v + (w ? sh[w - 1] : 0) + bsum[blockIdx.x];
    if (i < NN) {
        off[i] = excl;
        cur[i] = excl;
    }
}
__global__ void scatter_kernel(const int* __restrict__ ei, int* __restrict__ cur,
                               int* __restrict__ csr_src) {
    int i = blockIdx.x * blockDim.x + threadIdx.x;
    if (i >= ET) return;
    int src, dst;
    if (i < EE) { src = ei[i]; dst = ei[EE + i]; }
    else        { src = i - EE; dst = i - EE; }
    int pos = atomicAdd(&cur[dst], 1);
    csr_src[pos] = src;
}

// ---------------- bf16 HMMA GEMM, 2-term split: C = ah*(bh+bl) --------------
#define U32STR 68
#define REGION (128 * U32STR * 4)          // 34816 B
#define SM_A_HI 0
#define SM_B_HI REGION
#define SM_B_LO (2 * REGION)
#define GEMM_SMEM (3 * REGION)             // 104448 B
#define CSTR 132

__global__ __launch_bounds__(512, 1)
void gemm_tc_kernel(const float* __restrict__ A, const __nv_bfloat16* __restrict__ Bh,
                    const __nv_bfloat16* __restrict__ Bl, int M, int mode,
                    const float* __restrict__ p0, const float* __restrict__ p1,
                    const float* __restrict__ p2, float* __restrict__ out,
                    float* __restrict__ as_, float* __restrict__ ad_) {
    extern __shared__ char smem[];
    uint32_t* uAh = (uint32_t*)(smem + SM_A_HI);
    uint32_t* uBh = (uint32_t*)(smem + SM_B_HI);
    uint32_t* uBl = (uint32_t*)(smem + SM_B_LO);
    float* Cs = (float*)smem;

    const int tid = threadIdx.x, wid = tid >> 5, lane = tid & 31;
    const int g = lane >> 2, tig = lane & 3;
    const int rm = (wid >> 2) * 32;
    const int cn = (wid & 3) * 32;
    const int row0 = blockIdx.x * 128;

#pragma unroll
    for (int i = 0; i < 8; i++) {
        int idx = tid + i * 512;
        int r = idx >> 5;
        int c = (idx & 31) << 2;
        int gr = row0 + r;
        float4 v = make_float4(0.f, 0.f, 0.f, 0.f);
        if (gr < M) v = *(const float4*)(A + (long)gr * 128 + c);
        __nv_bfloat162 q0 = __floats2bfloat162_rn(v.x, v.y);
        __nv_bfloat162 q1 = __floats2bfloat162_rn(v.z, v.w);
        int o = r * U32STR + (c >> 1);
        uAh[o] = *(uint32_t*)&q0;
        uAh[o + 1] = *(uint32_t*)&q1;
    }
    const uint4* bhu = (const uint4*)Bh;
    const uint4* blu = (const uint4*)Bl;
#pragma unroll
    for (int i = 0; i < 4; i++) {
        int idx = tid + i * 512;
        int n = idx >> 4;
        int kg = (idx & 15) << 3;
        int o = n * U32STR + (kg >> 1);
        *(uint4*)(uBh + o) = bhu[idx];
        *(uint4*)(uBl + o) = blu[idx];
    }
    __syncthreads();

    float acc[2][4][4];
#pragma unroll
    for (int i = 0; i < 2; i++)
#pragma unroll
        for (int j = 0; j < 4; j++)
#pragma unroll
            for (int k = 0; k < 4; k++) acc[i][j][k] = 0.f;

#pragma unroll
    for (int ks = 0; ks < 8; ks++) {
        const int k32 = ks * 8 + tig;
        uint32_t ah[2][4], bh[4][2], bl[4][2];
#pragma unroll
        for (int mf = 0; mf < 2; mf++) {
            int r = rm + mf * 16 + g;
            ah[mf][0] = uAh[r * U32STR + k32];
            ah[mf][1] = uAh[(r + 8) * U32STR + k32];
            ah[mf][2] = uAh[r * U32STR + k32 + 4];
            ah[mf][3] = uAh[(r + 8) * U32STR + k32 + 4];
        }
#pragma unroll
        for (int nf = 0; nf < 4; nf++) {
            int c = cn + nf * 8 + g;
            bh[nf][0] = uBh[c * U32STR + k32];
            bh[nf][1] = uBh[c * U32STR + k32 + 4];
            bl[nf][0] = uBl[c * U32STR + k32];
            bl[nf][1] = uBl[c * U32STR + k32 + 4];
        }
#pragma unroll
        for (int mf = 0; mf < 2; mf++)
#pragma unroll
            for (int nf = 0; nf < 4; nf++) {
                mma_bf16(acc[mf][nf], ah[mf], bl[nf]);
                mma_bf16(acc[mf][nf], ah[mf], bh[nf]);
            }
    }
    __syncthreads();

#pragma unroll
    for (int mf = 0; mf < 2; mf++) {
        int r = rm + mf * 16 + g;
#pragma unroll
        for (int nf = 0; nf < 4; nf++) {
            int c = cn + nf * 8 + tig * 2;
            *(float2*)(Cs + r * CSTR + c) = make_float2(acc[mf][nf][0], acc[mf][nf][1]);
            *(float2*)(Cs + (r + 8) * CSTR + c) = make_float2(acc[mf][nf][2], acc[mf][nf][3]);
        }
    }
    __syncthreads();

    const int col = lane * 4;
#pragma unroll 1
    for (int i = 0; i < 8; i++) {
        int r = wid * 8 + i;
        int gr = row0 + r;
        if (gr >= M) break;
        float4 v = *(const float4*)(Cs + r * CSTR + col);
        if (mode == 0) {
            float4 b4 = *(const float4*)(p0 + col);
            v.x += b4.x; v.y += b4.y; v.z += b4.z; v.w += b4.w;
            float mu = warpSum(v.x + v.y + v.z + v.w) * (1.f / 128.f);
            float dx = v.x - mu, dy = v.y - mu, dz = v.z - mu, dw = v.w - mu;
            float var = warpSum(dx * dx + dy * dy + dz * dz + dw * dw) * (1.f / 128.f);
            float rs = rsqrtf(var + LN_EPS);
            float4 gv = *(const float4*)(p1 + col);
            float4 bv = *(const float4*)(p2 + col);
            float y;
            y = dx * rs * gv.x + bv.x; v.x = silu(y);
            y = dy * rs * gv.y + bv.y; v.y = silu(y);
            y = dz * rs * gv.z + bv.z; v.z = silu(y);
            y = dw * rs * gv.w + bv.w; v.w = silu(y);
            *(float4*)(out + (long)gr * 128 + col) = v;
        } else {
            *(float4*)(out + (long)gr * 128 + col) = v;
            float4 w1 = *(const float4*)(p0 + col);
            float4 w2 = *(const float4*)(p1 + col);
            float sa = v.x * w1.x + v.y * w1.y + v.z * w1.z + v.w * w1.w;
            float sd = v.x * w2.x + v.y * w2.y + v.z * w2.z + v.w * w2.w;
#pragma unroll
            for (int o = 4; o > 0; o >>= 1) {
                sa += __shfl_xor_sync(0xffffffffu, sa, o);
                sd += __shfl_xor_sync(0xffffffffu, sd, o);
            }
            float a0 = __shfl_sync(0xffffffffu, sa, 0);
            float a1 = __shfl_sync(0xffffffffu, sa, 8);
            float a2 = __shfl_sync(0xffffffffu, sa, 16);
            float a3 = __shfl_sync(0xffffffffu, sa, 24);
            float d0 = __shfl_sync(0xffffffffu, sd, 0);
            float d1 = __shfl_sync(0xffffffffu, sd, 8);
            float d2 = __shfl_sync(0xffffffffu, sd, 16);
            float d3 = __shfl_sync(0xffffffffu, sd, 24);
            if (lane == 0) {
                *(float4*)(as_ + gr * 4) = make_float4(a0, a1, a2, a3);
                *(float4*)(ad_ + gr * 4) = make_float4(d0, d1, d2, d3);
            }
        }
    }
}

// -------- GAT aggregate v1 + unroll-4 gather (MLP fix) ---------------------
__global__ void gat_aggregate_kernel(const float* __restrict__ hh, const float* __restrict__ a_s,
                                     const float* __restrict__ a_d, const int* __restrict__ off,
                                     const int* __restrict__ csr_src, const float* __restrict__ bg,
                                     const float* __restrict__ gg, const float* __restrict__ bgg,
                                     float* __restrict__ h) {
    int n = (blockIdx.x * blockDim.x + threadIdx.x) >> 5;
    if (n >= NN) return;
    int lane = threadIdx.x & 31;
    int beg = off[n], end = off[n + 1];

    float4 adv = *(const float4*)(a_d + n * 4);
    float m0 = -1e30f, m1 = -1e30f, m2 = -1e30f, m3 = -1e30f;
    float s0 = 0.f, s1 = 0.f, s2 = 0.f, s3 = 0.f;
    for (int j = beg + lane; j < end; j += 32) {
        int s = csr_src[j];
        float4 asv = *(const float4*)(a_s + s * 4);
        float e;
        e = lrelu(asv.x + adv.x);
        if (e > m0) { s0 = s0 * __expf(m0 - e) + 1.f; m0 = e; } else s0 += __expf(e - m0);
        e = lrelu(asv.y + adv.y);
        if (e > m1) { s1 = s1 * __expf(m1 - e) + 1.f; m1 = e; } else s1 += __expf(e - m1);
        e = lrelu(asv.z + adv.z);
        if (e > m2) { s2 = s2 * __expf(m2 - e) + 1.f; m2 = e; } else s2 += __expf(e - m2);
        e = lrelu(asv.w + adv.w);
        if (e > m3) { s3 = s3 * __expf(m3 - e) + 1.f; m3 = e; } else s3 += __expf(e - m3);
    }
#pragma unroll
    for (int o = 16; o > 0; o >>= 1) {
        float om, os, nm;
        om = __shfl_xor_sync(0xffffffffu, m0, o); os = __shfl_xor_sync(0xffffffffu, s0, o);
        nm = fmaxf(m0, om); s0 = s0 * __expf(m0 - nm) + os * __expf(om - nm); m0 = nm;
        om = __shfl_xor_sync(0xffffffffu, m1, o); os = __shfl_xor_sync(0xffffffffu, s1, o);
        nm = fmaxf(m1, om); s1 = s1 * __expf(m1 - nm) + os * __expf(om - nm); m1 = nm;
        om = __shfl_xor_sync(0xffffffffu, m2, o); os = __shfl_xor_sync(0xffffffffu, s2, o);
        nm = fmaxf(m2, om); s2 = s2 * __expf(m2 - nm) + os * __expf(om - nm); m2 = nm;
        om = __shfl_xor_sync(0xffffffffu, m3, o); os = __shfl_xor_sync(0xffffffffu, s3, o);
        nm = fmaxf(m3, om); s3 = s3 * __expf(m3 - nm) + os * __expf(om - nm); m3 = nm;
    }

    int hd = lane >> 3;
    float mh   = (hd == 0) ? m0 : (hd == 1) ? m1 : (hd == 2) ? m2 : m3;
    float adh  = (hd == 0) ? adv.x : (hd == 1) ? adv.y : (hd == 2) ? adv.z : adv.w;
    float invh = 1.f / ((hd == 0) ? s0 : (hd == 1) ? s1 : (hd == 2) ? s2 : s3);

    const int col = lane * 4;
    float4 acc = make_float4(0.f, 0.f, 0.f, 0.f);
    // unroll-4: batch independent loads before exp/FMA work (MLP ~8)
    int j = beg;
    for (; j + 3 < end; j += 4) {
        int sa0 = csr_src[j], sa1 = csr_src[j + 1];
        int sa2 = csr_src[j + 2], sa3 = csr_src[j + 3];
        float l0 = a_s[sa0 * 4 + hd], l1 = a_s[sa1 * 4 + hd];
        float l2 = a_s[sa2 * 4 + hd], l3 = a_s[sa3 * 4 + hd];
        float4 v0 = *(const float4*)(hh + (long)sa0 * 128 + col);
        float4 v1 = *(const float4*)(hh + (long)sa1 * 128 + col);
        float4 v2 = *(const float4*)(hh + (long)sa2 * 128 + col);
        float4 v3 = *(const float4*)(hh + (long)sa3 * 128 + col);
        float w0 = __expf(lrelu(l0 + adh) - mh) * invh;
        float w1 = __expf(lrelu(l1 + adh) - mh) * invh;
        float w2 = __expf(lrelu(l2 + adh) - mh) * invh;
        float w3 = __expf(lrelu(l3 + adh) - mh) * invh;
        acc.x += v0.x * w0; acc.y += v0.y * w0; acc.z += v0.z * w0; acc.w += v0.w * w0;
        acc.x += v1.x * w1; acc.y += v1.y * w1; acc.z += v1.z * w1; acc.w += v1.w * w1;
        acc.x += v2.x * w2; acc.y += v2.y * w2; acc.z += v2.z * w2; acc.w += v2.w * w2;
        acc.x += v3.x * w3; acc.y += v3.y * w3; acc.z += v3.z * w3; acc.w += v3.w * w3;
    }
    for (; j < end; j++) {
        int s = csr_src[j];
        float w = __expf(lrelu(a_s[s * 4 + hd] + adh) - mh) * invh;
        float4 v = *(const float4*)(hh + (long)s * 128 + col);
        acc.x += v.x * w; acc.y += v.y * w; acc.z += v.z * w; acc.w += v.w * w;
    }
    float4 bgv = *(const float4*)(bg + col);
    acc.x += bgv.x; acc.y += bgv.y; acc.z += bgv.z; acc.w += bgv.w;
    float mu = warpSum(acc.x + acc.y + acc.z + acc.w) * (1.f / 128.f);
    float dx = acc.x - mu, dy = acc.y - mu, dz = acc.z - mu, dw = acc.w - mu;
    float var = warpSum(dx * dx + dy * dy + dz * dz + dw * dw) * (1.f / 128.f);
    float r = rsqrtf(var + LN_EPS);
    float4 gv  = *(const float4*)(gg + col);
    float4 bv  = *(const float4*)(bgg + col);
    float4 old = *(const float4*)(h + (long)n * 128 + col);
    float y;
    y = dx * r * gv.x + bv.x; acc.x = silu(y) + old.x;
    y = dy * r * gv.y + bv.y; acc.y = silu(y) + old.y;
    y = dz * r * gv.z + bv.z; acc.z = silu(y) + old.z;
    y = dw * r * gv.w + bv.w; acc.w = silu(y) + old.w;
    *(float4*)(h + (long)n * 128 + col) = acc;
}

// -------- fused pool (sorted batch) + projection + LN + SiLU, 512 thr -----
__global__ __launch_bounds__(512)
void pool_final_kernel(const float* __restrict__ h, const int* __restrict__ batch,
                       const float* __restrict__ Wp, const float* __restrict__ bp,
                       const float* __restrict__ gp, const float* __restrict__ bep,
                       float* __restrict__ out) {
    __shared__ float part[4][128];
    __shared__ float p[128];
    __shared__ float accv[128];
    __shared__ float sh[4];
    __shared__ int bounds[2];
    int b = blockIdx.x, t = threadIdx.x;
    int col = t & 127, q = t >> 7;
    int lane = t & 31;
    if (t < 2) {
        int target = b + t;
        int lo = 0, hi = NN;
        while (lo < hi) {
            int mid = (lo + hi) >> 1;
            if (batch[mid] < target) lo = mid + 1; else hi = mid;
        }
        bounds[t] = lo;
    }
    __syncthreads();
    int lo = bounds[0], hi = bounds[1];
    float s = 0.f;
    for (int n = lo + q; n < hi; n += 4) s += h[(long)n * 128 + col];
    part[q][col] = s;
    __syncthreads();
    if (t < 128) {
        float c = (float)(hi - lo > 0 ? hi - lo : 1);
        p[t] = (part[0][t] + part[1][t] + part[2][t] + part[3][t]) / c;
    }
    __syncthreads();
    float ap = 0.f;
#pragma unroll 8
    for (int k = q * 32; k < q * 32 + 32; k++) ap += p[k] * Wp[k * 128 + col];
    part[q][col] = ap;
    __syncthreads();
    if (t < 128) accv[t] = part[0][t] + part[1][t] + part[2][t] + part[3][t] + bp[t];
    __syncthreads();
    float a = accv[col];
    float v = warpSum(a);
    if (t < 128 && lane == 0) sh[t >> 5] = v;
    __syncthreads();
    float mu = (sh[0] + sh[1] + sh[2] + sh[3]) * (1.f / 128.f);
    float d = a - mu;
    v = warpSum(d * d);
    __syncthreads();
    if (t < 128 && lane == 0) sh[t >> 5] = v;
    __syncthreads();
    float var = (sh[0] + sh[1] + sh[2] + sh[3]) * (1.f / 128.f);
    if (t < 128) {
        float r = rsqrtf(var + LN_EPS);
        float y = d * r * gp[t] + bep[t];
        out[b * 128 + t] = silu(y);
    }
}

// ---------------- launch ----------------
extern "C" void kernel_launch(void* const* d_in, const int* in_sizes, int n_in,
                              void* d_out, int out_size) {
    const float* x       = (const float*)d_in[0];
    const int*   ei      = (const int*)d_in[1];
    const int*   batch   = (const int*)d_in[2];
    const float* W0      = (const float*)d_in[3];
    const float* b0      = (const float*)d_in[4];
    const float* g0      = (const float*)d_in[5];
    const float* be0     = (const float*)d_in[6];
    const float* Wg      = (const float*)d_in[7];
    const float* att_src = (const float*)d_in[8];
    const float* att_dst = (const float*)d_in[9];
    const float* bg      = (const float*)d_in[10];
    const float* gg      = (const float*)d_in[11];
    const float* bgg     = (const float*)d_in[12];
    const float* Wp      = (const float*)d_in[13];
    const float* bp      = (const float*)d_in[14];
    const float* gp      = (const float*)d_in[15];
    const float* bep     = (const float*)d_in[16];
    float* out = (float*)d_out;

    float *h, *tmp, *as_, *ad_;
    int *deg, *off, *cur, *csr, *bsum;
    __nv_bfloat16 *wh, *wl;
    cudaGetSymbolAddress((void**)&h, g_h);
    cudaGetSymbolAddress((void**)&tmp, g_tmp);
    cudaGetSymbolAddress((void**)&as_, g_as);
    cudaGetSymbolAddress((void**)&ad_, g_ad);
    cudaGetSymbolAddress((void**)&deg, g_deg);
    cudaGetSymbolAddress((void**)&off, g_off);
    cudaGetSymbolAddress((void**)&cur, g_cur);
    cudaGetSymbolAddress((void**)&csr, g_csr_src);
    cudaGetSymbolAddress((void**)&bsum, g_bsum);
    cudaGetSymbolAddress((void**)&wh, g_wT_hi);
    cudaGetSymbolAddress((void**)&wl, g_wT_lo);

    cudaFuncSetAttribute(gemm_tc_kernel, cudaFuncAttributeMaxDynamicSharedMemorySize,
                         GEMM_SMEM);
    const int GEMM_GRID = (NN + 127) / 128;

    // launch order: index 3 = encoder GEMM (ncu capture slot)
    wprep_kernel<<<(4 * HID * HID + 255) / 256, 256>>>(W0, Wg, wh, wl);       // 0
    zero_deg_kernel<<<(NN + 255) / 256, 256>>>(deg);                          // 1
    count_deg_kernel<<<(ET + 255) / 256, 256>>>(ei, deg);                     // 2
    gemm_tc_kernel<<<GEMM_GRID, 512, GEMM_SMEM>>>(x, wh, wl, NN, 0,           // 3
                                                  b0, g0, be0, h, nullptr, nullptr);
    scan_part_kernel<<<NBLK, SCAN_BLK>>>(deg, bsum);                          // 4
    scan_top_kernel<<<1, 256>>>(bsum, off);                                   // 5
    scan_add_kernel<<<NBLK, SCAN_BLK>>>(deg, bsum, off, cur);                 // 6
    scatter_kernel<<<(ET + 255) / 256, 256>>>(ei, cur, csr);                  // 7

    for (int l = 0; l < LAYERS; l++) {
        gemm_tc_kernel<<<GEMM_GRID, 512, GEMM_SMEM>>>(
            h, wh + (l + 1) * HID * HID, wl + (l + 1) * HID * HID, NN, 1,
            att_src + l * 128, att_dst + l * 128, nullptr, tmp, as_, ad_);
        gat_aggregate_kernel<<<(NN * 32 + 255) / 256, 256>>>(
            tmp, as_, ad_, off, csr, bg + l * 128, gg + l * 128, bgg + l * 128, h);
    }

    pool_final_kernel<<<NB, 512>>>(h, batch, Wp, bp, gp, bep, out);
}

// round 14
// speedup vs baseline: 1.1169x; 1.1169x over previous
#include <cuda_runtime.h>
#include <cuda_bf16.h>
#include <cstdint>

#define NN      50000
#define EE      800000
#define ET      850000
#define HID     128
#define HEADS   4
#define NB      64
#define LAYERS  3
#define LN_EPS  1e-5f
#define NEG_SLOPE 0.2f

#define SCAN_BLK 256
#define NBLK ((NN + SCAN_BLK - 1) / SCAN_BLK)   // 196

// ---------------- device scratch ----------------
__device__ float g_h[NN * HID];
__device__ float g_tmp[NN * HID];
__device__ float g_as[NN * HEADS];
__device__ float g_ad[NN * HEADS];
__device__ int   g_deg[NN];
__device__ int   g_off[NN + 1];
__device__ int   g_cur[NN];
__device__ int   g_bsum[NBLK];
__device__ int   g_csr_src[ET];
__device__ __nv_bfloat16 g_wT_hi[4 * HID * HID];  // [w][n][k] = W[k][n] hi
__device__ __nv_bfloat16 g_wT_lo[4 * HID * HID];

// ---------------- helpers ----------------
__device__ __forceinline__ float warpSum(float v) {
#pragma unroll
    for (int o = 16; o > 0; o >>= 1) v += __shfl_xor_sync(0xffffffffu, v, o);
    return v;
}
__device__ __forceinline__ float warpMax(float v) {
#pragma unroll
    for (int o = 16; o > 0; o >>= 1) v = fmaxf(v, __shfl_xor_sync(0xffffffffu, v, o));
    return v;
}
__device__ __forceinline__ int warpSumI(int v) {
#pragma unroll
    for (int o = 16; o > 0; o >>= 1) v += __shfl_xor_sync(0xffffffffu, v, o);
    return v;
}
__device__ __forceinline__ int warpScanIncl(int x, int lane) {
#pragma unroll
    for (int o = 1; o < 32; o <<= 1) {
        int t = __shfl_up_sync(0xffffffffu, x, o);
        if (lane >= o) x += t;
    }
    return x;
}
__device__ __forceinline__ float lrelu(float x) { return x > 0.f ? x : NEG_SLOPE * x; }
__device__ __forceinline__ float silu(float x) { return x / (1.f + __expf(-x)); }

__device__ __forceinline__ void mma_bf16(float* c, const uint32_t* a, const uint32_t* b) {
    asm volatile(
        "mma.sync.aligned.m16n8k16.row.col.f32.bf16.bf16.f32 "
        "{%0,%1,%2,%3},{%4,%5,%6,%7},{%8,%9},{%0,%1,%2,%3};"
        : "+f"(c[0]), "+f"(c[1]), "+f"(c[2]), "+f"(c[3])
        : "r"(a[0]), "r"(a[1]), "r"(a[2]), "r"(a[3]), "r"(b[0]), "r"(b[1]));
}

__device__ __forceinline__ void split_pack(float a, float b, uint32_t& h, uint32_t& l) {
    __nv_bfloat16 ha = __float2bfloat16(a), hb = __float2bfloat16(b);
    __nv_bfloat162 hv = __halves2bfloat162(ha, hb);
    __nv_bfloat162 lv = __floats2bfloat162_rn(a - __bfloat162float(ha),
                                              b - __bfloat162float(hb));
    h = *(uint32_t*)&hv;
    l = *(uint32_t*)&lv;
}

// ---------------- weight prep: W^T split into bf16 hi/lo ----------------
__global__ void wprep_kernel(const float* __restrict__ W0, const float* __restrict__ Wg,
                             __nv_bfloat16* __restrict__ bh, __nv_bfloat16* __restrict__ bl) {
    int i = blockIdx.x * blockDim.x + threadIdx.x;
    if (i >= 4 * HID * HID) return;
    int w = i >> 14, rem = i & 16383, n = rem >> 7, k = rem & 127;
    const float* src = (w == 0) ? W0 : (Wg + (w - 1) * HID * HID);
    float v = src[k * HID + n];
    __nv_bfloat16 hi = __float2bfloat16(v);
    bh[i] = hi;
    bl[i] = __float2bfloat16(v - __bfloat162float(hi));
}

// ---------------- CSR build ----------------
__global__ void zero_deg_kernel(int* deg) {
    int i = blockIdx.x * blockDim.x + threadIdx.x;
    if (i < NN) deg[i] = 0;
}
__global__ void count_deg_kernel(const int* __restrict__ ei, int* __restrict__ deg) {
    int i = blockIdx.x * blockDim.x + threadIdx.x;
    if (i >= ET) return;
    int dst = (i < EE) ? ei[EE + i] : (i - EE);
    atomicAdd(&deg[dst], 1);
}
__global__ void scan_part_kernel(const int* __restrict__ deg, int* __restrict__ bsum) {
    __shared__ int sh[SCAN_BLK / 32];
    int tid = threadIdx.x, lane = tid & 31, w = tid >> 5;
    int i = blockIdx.x * SCAN_BLK + tid;
    int v = (i < NN) ? deg[i] : 0;
    int s = warpSumI(v);
    if (lane == 0) sh[w] = s;
    __syncthreads();
    if (w == 0) {
        int t = (lane < SCAN_BLK / 32) ? sh[lane] : 0;
        t = warpSumI(t);
        if (lane == 0) bsum[blockIdx.x] = t;
    }
}
__global__ void scan_top_kernel(int* __restrict__ bsum, int* __restrict__ off) {
    __shared__ int sh[8];
    int tid = threadIdx.x, lane = tid & 31, w = tid >> 5;
    int v = (tid < NBLK) ? bsum[tid] : 0;
    int x = warpScanIncl(v, lane);
    if (lane == 31) sh[w] = x;
    __syncthreads();
    if (w == 0) {
        int t = (lane < 8) ? sh[lane] : 0;
        t = warpScanIncl(t, lane);
        if (lane < 8) sh[lane] = t;
    }
    __syncthreads();
    int incl = x + (w ? sh[w - 1] : 0);
    if (tid < NBLK) bsum[tid] = incl - v;
    if (tid == NBLK - 1) off[NN] = incl;
}
__global__ void scan_add_kernel(const int* __restrict__ deg, const int* __restrict__ bsum,
                                int* __restrict__ off, int* __restrict__ cur) {
    __shared__ int sh[SCAN_BLK / 32];
    int tid = threadIdx.x, lane = tid & 31, w = tid >> 5;
    int i = blockIdx.x * SCAN_BLK + tid;
    int v = (i < NN) ? deg[i] : 0;
    int x = warpScanIncl(v, lane);
    if (lane == 31) sh[w] = x;
    __syncthreads();
    if (w == 0) {
        int t = (lane < SCAN_BLK / 32) ? sh[lane] : 0;
        t = warpScanIncl(t, lane);
        if (lane < SCAN_BLK / 32) sh[lane] = t;
    }
    __syncthreads();
    int excl = x - v + (w ? sh[w - 1] : 0) + bsum[blockIdx.x];
    if (i < NN) {
        off[i] = excl;
        cur[i] = excl;
    }
}
__global__ void scatter_kernel(const int* __restrict__ ei, int* __restrict__ cur,
                               int* __restrict__ csr_src) {
    int i = blockIdx.x * blockDim.x + threadIdx.x;
    if (i >= ET) return;
    int src, dst;
    if (i < EE) { src = ei[i]; dst = ei[EE + i]; }
    else        { src = i - EE; dst = i - EE; }
    int pos = atomicAdd(&cur[dst], 1);
    csr_src[pos] = src;
}

// ---------------- bf16 HMMA GEMM, 2-term split: C = ah*(bh+bl) --------------
#define U32STR 68
#define REGION (128 * U32STR * 4)          // 34816 B
#define SM_A_HI 0
#define SM_B_HI REGION
#define SM_B_LO (2 * REGION)
#define GEMM_SMEM (3 * REGION)             // 104448 B
#define CSTR 132

__global__ __launch_bounds__(512, 1)
void gemm_tc_kernel(const float* __restrict__ A, const __nv_bfloat16* __restrict__ Bh,
                    const __nv_bfloat16* __restrict__ Bl, int M, int mode,
                    const float* __restrict__ p0, const float* __restrict__ p1,
                    const float* __restrict__ p2, float* __restrict__ out,
                    float* __restrict__ as_, float* __restrict__ ad_) {
    extern __shared__ char smem[];
    uint32_t* uAh = (uint32_t*)(smem + SM_A_HI);
    uint32_t* uBh = (uint32_t*)(smem + SM_B_HI);
    uint32_t* uBl = (uint32_t*)(smem + SM_B_LO);
    float* Cs = (float*)smem;

    const int tid = threadIdx.x, wid = tid >> 5, lane = tid & 31;
    const int g = lane >> 2, tig = lane & 3;
    const int rm = (wid >> 2) * 32;
    const int cn = (wid & 3) * 32;
    const int row0 = blockIdx.x * 128;

#pragma unroll
    for (int i = 0; i < 8; i++) {
        int idx = tid + i * 512;
        int r = idx >> 5;
        int c = (idx & 31) << 2;
        int gr = row0 + r;
        float4 v = make_float4(0.f, 0.f, 0.f, 0.f);
        if (gr < M) v = *(const float4*)(A + (long)gr * 128 + c);
        __nv_bfloat162 q0 = __floats2bfloat162_rn(v.x, v.y);
        __nv_bfloat162 q1 = __floats2bfloat162_rn(v.z, v.w);
        int o = r * U32STR + (c >> 1);
        uAh[o] = *(uint32_t*)&q0;
        uAh[o + 1] = *(uint32_t*)&q1;
    }
    const uint4* bhu = (const uint4*)Bh;
    const uint4* blu = (const uint4*)Bl;
#pragma unroll
    for (int i = 0; i < 4; i++) {
        int idx = tid + i * 512;
        int n = idx >> 4;
        int kg = (idx & 15) << 3;
        int o = n * U32STR + (kg >> 1);
        *(uint4*)(uBh + o) = bhu[idx];
        *(uint4*)(uBl + o) = blu[idx];
    }
    __syncthreads();

    float acc[2][4][4];
#pragma unroll
    for (int i = 0; i < 2; i++)
#pragma unroll
        for (int j = 0; j < 4; j++)
#pragma unroll
            for (int k = 0; k < 4; k++) acc[i][j][k] = 0.f;

#pragma unroll
    for (int ks = 0; ks < 8; ks++) {
        const int k32 = ks * 8 + tig;
        uint32_t ah[2][4], bh[4][2], bl[4][2];
#pragma unroll
        for (int mf = 0; mf < 2; mf++) {
            int r = rm + mf * 16 + g;
            ah[mf][0] = uAh[r * U32STR + k32];
            ah[mf][1] = uAh[(r + 8) * U32STR + k32];
            ah[mf][2] = uAh[r * U32STR + k32 + 4];
            ah[mf][3] = uAh[(r + 8) * U32STR + k32 + 4];
        }
#pragma unroll
        for (int nf = 0; nf < 4; nf++) {
            int c = cn + nf * 8 + g;
            bh[nf][0] = uBh[c * U32STR + k32];
            bh[nf][1] = uBh[c * U32STR + k32 + 4];
            bl[nf][0] = uBl[c * U32STR + k32];
            bl[nf][1] = uBl[c * U32STR + k32 + 4];
        }
#pragma unroll
        for (int mf = 0; mf < 2; mf++)
#pragma unroll
            for (int nf = 0; nf < 4; nf++) {
                mma_bf16(acc[mf][nf], ah[mf], bl[nf]);
                mma_bf16(acc[mf][nf], ah[mf], bh[nf]);
            }
    }
    __syncthreads();

#pragma unroll
    for (int mf = 0; mf < 2; mf++) {
        int r = rm + mf * 16 + g;
#pragma unroll
        for (int nf = 0; nf < 4; nf++) {
            int c = cn + nf * 8 + tig * 2;
            *(float2*)(Cs + r * CSTR + c) = make_float2(acc[mf][nf][0], acc[mf][nf][1]);
            *(float2*)(Cs + (r + 8) * CSTR + c) = make_float2(acc[mf][nf][2], acc[mf][nf][3]);
        }
    }
    __syncthreads();

    const int col = lane * 4;
#pragma unroll 1
    for (int i = 0; i < 8; i++) {
        int r = wid * 8 + i;
        int gr = row0 + r;
        if (gr >= M) break;
        float4 v = *(const float4*)(Cs + r * CSTR + col);
        if (mode == 0) {
            float4 b4 = *(const float4*)(p0 + col);
            v.x += b4.x; v.y += b4.y; v.z += b4.z; v.w += b4.w;
            float mu = warpSum(v.x + v.y + v.z + v.w) * (1.f / 128.f);
            float dx = v.x - mu, dy = v.y - mu, dz = v.z - mu, dw = v.w - mu;
            float var = warpSum(dx * dx + dy * dy + dz * dz + dw * dw) * (1.f / 128.f);
            float rs = rsqrtf(var + LN_EPS);
            float4 gv = *(const float4*)(p1 + col);
            float4 bv = *(const float4*)(p2 + col);
            float y;
            y = dx * rs * gv.x + bv.x; v.x = silu(y);
            y = dy * rs * gv.y + bv.y; v.y = silu(y);
            y = dz * rs * gv.z + bv.z; v.z = silu(y);
            y = dw * rs * gv.w + bv.w; v.w = silu(y);
            *(float4*)(out + (long)gr * 128 + col) = v;
        } else {
            *(float4*)(out + (long)gr * 128 + col) = v;
            float4 w1 = *(const float4*)(p0 + col);
            float4 w2 = *(const float4*)(p1 + col);
            float sa = v.x * w1.x + v.y * w1.y + v.z * w1.z + v.w * w1.w;
            float sd = v.x * w2.x + v.y * w2.y + v.z * w2.z + v.w * w2.w;
#pragma unroll
            for (int o = 4; o > 0; o >>= 1) {
                sa += __shfl_xor_sync(0xffffffffu, sa, o);
                sd += __shfl_xor_sync(0xffffffffu, sd, o);
            }
            float a0 = __shfl_sync(0xffffffffu, sa, 0);
            float a1 = __shfl_sync(0xffffffffu, sa, 8);
            float a2 = __shfl_sync(0xffffffffu, sa, 16);
            float a3 = __shfl_sync(0xffffffffu, sa, 24);
            float d0 = __shfl_sync(0xffffffffu, sd, 0);
            float d1 = __shfl_sync(0xffffffffu, sd, 8);
            float d2 = __shfl_sync(0xffffffffu, sd, 16);
            float d3 = __shfl_sync(0xffffffffu, sd, 24);
            if (lane == 0) {
                *(float4*)(as_ + gr * 4) = make_float4(a0, a1, a2, a3);
                *(float4*)(ad_ + gr * 4) = make_float4(d0, d1, d2, d3);
            }
        }
    }
}

// -------- GAT aggregate: register-cached softmax stats (no exp in reductions)
// + round-11 pass-3 gather + LN + SiLU + residual. Warp per dst node.
__global__ void gat_aggregate_kernel(const float* __restrict__ hh, const float* __restrict__ a_s,
                                     const float* __restrict__ a_d, const int* __restrict__ off,
                                     const int* __restrict__ csr_src, const float* __restrict__ bg,
                                     const float* __restrict__ gg, const float* __restrict__ bgg,
                                     float* __restrict__ h) {
    int n = (blockIdx.x * blockDim.x + threadIdx.x) >> 5;
    if (n >= NN) return;
    int lane = threadIdx.x & 31;
    int beg = off[n], end = off[n + 1];
    int cnt = end - beg;

    float4 adv = *(const float4*)(a_d + n * 4);
    // chunk-0 edge logits cached in registers (deg<=32 common case)
    float e0 = -1e30f, e1 = -1e30f, e2 = -1e30f, e3 = -1e30f;
    if (lane < cnt) {
        int s = csr_src[beg + lane];
        float4 asv = *(const float4*)(a_s + s * 4);
        e0 = lrelu(asv.x + adv.x);
        e1 = lrelu(asv.y + adv.y);
        e2 = lrelu(asv.z + adv.z);
        e3 = lrelu(asv.w + adv.w);
    }
    float lm0 = e0, lm1 = e1, lm2 = e2, lm3 = e3;
    for (int j = beg + 32 + lane; j < end; j += 32) {   // rare: deg > 32
        int s = csr_src[j];
        float4 asv = *(const float4*)(a_s + s * 4);
        lm0 = fmaxf(lm0, lrelu(asv.x + adv.x));
        lm1 = fmaxf(lm1, lrelu(asv.y + adv.y));
        lm2 = fmaxf(lm2, lrelu(asv.z + adv.z));
        lm3 = fmaxf(lm3, lrelu(asv.w + adv.w));
    }
    float m0 = warpMax(lm0), m1 = warpMax(lm1), m2 = warpMax(lm2), m3 = warpMax(lm3);

    float s0 = (lane < cnt) ? __expf(e0 - m0) : 0.f;
    float s1 = (lane < cnt) ? __expf(e1 - m1) : 0.f;
    float s2 = (lane < cnt) ? __expf(e2 - m2) : 0.f;
    float s3 = (lane < cnt) ? __expf(e3 - m3) : 0.f;
    for (int j = beg + 32 + lane; j < end; j += 32) {   // rare
        int s = csr_src[j];
        float4 asv = *(const float4*)(a_s + s * 4);
        s0 += __expf(lrelu(asv.x + adv.x) - m0);
        s1 += __expf(lrelu(asv.y + adv.y) - m1);
        s2 += __expf(lrelu(asv.z + adv.z) - m2);
        s3 += __expf(lrelu(asv.w + adv.w) - m3);
    }
    s0 = warpSum(s0); s1 = warpSum(s1); s2 = warpSum(s2); s3 = warpSum(s3);

    int hd = lane >> 3;
    float mh   = (hd == 0) ? m0 : (hd == 1) ? m1 : (hd == 2) ? m2 : m3;
    float adh  = (hd == 0) ? adv.x : (hd == 1) ? adv.y : (hd == 2) ? adv.z : adv.w;
    float invh = 1.f / ((hd == 0) ? s0 : (hd == 1) ? s1 : (hd == 2) ? s2 : s3);

    const int col = lane * 4;
    float4 acc = make_float4(0.f, 0.f, 0.f, 0.f);
    for (int j = beg; j < end; j++) {
        int s = csr_src[j];
        float w = __expf(lrelu(a_s[s * 4 + hd] + adh) - mh) * invh;
        float4 v = *(const float4*)(hh + (long)s * 128 + col);
        acc.x += v.x * w; acc.y += v.y * w; acc.z += v.z * w; acc.w += v.w * w;
    }
    float4 bgv = *(const float4*)(bg + col);
    acc.x += bgv.x; acc.y += bgv.y; acc.z += bgv.z; acc.w += bgv.w;
    float mu = warpSum(acc.x + acc.y + acc.z + acc.w) * (1.f / 128.f);
    float dx = acc.x - mu, dy = acc.y - mu, dz = acc.z - mu, dw = acc.w - mu;
    float var = warpSum(dx * dx + dy * dy + dz * dz + dw * dw) * (1.f / 128.f);
    float r = rsqrtf(var + LN_EPS);
    float4 gv  = *(const float4*)(gg + col);
    float4 bv  = *(const float4*)(bgg + col);
    float4 old = *(const float4*)(h + (long)n * 128 + col);
    float y;
    y = dx * r * gv.x + bv.x; acc.x = silu(y) + old.x;
    y = dy * r * gv.y + bv.y; acc.y = silu(y) + old.y;
    y = dz * r * gv.z + bv.z; acc.z = silu(y) + old.z;
    y = dw * r * gv.w + bv.w; acc.w = silu(y) + old.w;
    *(float4*)(h + (long)n * 128 + col) = acc;
}

// -------- fused pool (sorted batch) + projection + LN + SiLU, 512 thr -----
__global__ __launch_bounds__(512)
void pool_final_kernel(const float* __restrict__ h, const int* __restrict__ batch,
                       const float* __restrict__ Wp, const float* __restrict__ bp,
                       const float* __restrict__ gp, const float* __restrict__ bep,
                       float* __restrict__ out) {
    __shared__ float part[4][128];
    __shared__ float p[128];
    __shared__ float accv[128];
    __shared__ float sh[4];
    __shared__ int bounds[2];
    int b = blockIdx.x, t = threadIdx.x;
    int col = t & 127, q = t >> 7;
    int lane = t & 31;
    if (t < 2) {
        int target = b + t;
        int lo = 0, hi = NN;
        while (lo < hi) {
            int mid = (lo + hi) >> 1;
            if (batch[mid] < target) lo = mid + 1; else hi = mid;
        }
        bounds[t] = lo;
    }
    __syncthreads();
    int lo = bounds[0], hi = bounds[1];
    float s = 0.f;
    for (int n = lo + q; n < hi; n += 4) s += h[(long)n * 128 + col];
    part[q][col] = s;
    __syncthreads();
    if (t < 128) {
        float c = (float)(hi - lo > 0 ? hi - lo : 1);
        p[t] = (part[0][t] + part[1][t] + part[2][t] + part[3][t]) / c;
    }
    __syncthreads();
    float ap = 0.f;
#pragma unroll 8
    for (int k = q * 32; k < q * 32 + 32; k++) ap += p[k] * Wp[k * 128 + col];
    part[q][col] = ap;
    __syncthreads();
    if (t < 128) accv[t] = part[0][t] + part[1][t] + part[2][t] + part[3][t] + bp[t];
    __syncthreads();
    float a = accv[col];
    float v = warpSum(a);
    if (t < 128 && lane == 0) sh[t >> 5] = v;
    __syncthreads();
    float mu = (sh[0] + sh[1] + sh[2] + sh[3]) * (1.f / 128.f);
    float d = a - mu;
    v = warpSum(d * d);
    __syncthreads();
    if (t < 128 && lane == 0) sh[t >> 5] = v;
    __syncthreads();
    float var = (sh[0] + sh[1] + sh[2] + sh[3]) * (1.f / 128.f);
    if (t < 128) {
        float r = rsqrtf(var + LN_EPS);
        float y = d * r * gp[t] + bep[t];
        out[b * 128 + t] = silu(y);
    }
}

// ---------------- launch ----------------
extern "C" void kernel_launch(void* const* d_in, const int* in_sizes, int n_in,
                              void* d_out, int out_size) {
    const float* x       = (const float*)d_in[0];
    const int*   ei      = (const int*)d_in[1];
    const int*   batch   = (const int*)d_in[2];
    const float* W0      = (const float*)d_in[3];
    const float* b0      = (const float*)d_in[4];
    const float* g0      = (const float*)d_in[5];
    const float* be0     = (const float*)d_in[6];
    const float* Wg      = (const float*)d_in[7];
    const float* att_src = (const float*)d_in[8];
    const float* att_dst = (const float*)d_in[9];
    const float* bg      = (const float*)d_in[10];
    const float* gg      = (const float*)d_in[11];
    const float* bgg     = (const float*)d_in[12];
    const float* Wp      = (const float*)d_in[13];
    const float* bp      = (const float*)d_in[14];
    const float* gp      = (const float*)d_in[15];
    const float* bep     = (const float*)d_in[16];
    float* out = (float*)d_out;

    float *h, *tmp, *as_, *ad_;
    int *deg, *off, *cur, *csr, *bsum;
    __nv_bfloat16 *wh, *wl;
    cudaGetSymbolAddress((void**)&h, g_h);
    cudaGetSymbolAddress((void**)&tmp, g_tmp);
    cudaGetSymbolAddress((void**)&as_, g_as);
    cudaGetSymbolAddress((void**)&ad_, g_ad);
    cudaGetSymbolAddress((void**)&deg, g_deg);
    cudaGetSymbolAddress((void**)&off, g_off);
    cudaGetSymbolAddress((void**)&cur, g_cur);
    cudaGetSymbolAddress((void**)&csr, g_csr_src);
    cudaGetSymbolAddress((void**)&bsum, g_bsum);
    cudaGetSymbolAddress((void**)&wh, g_wT_hi);
    cudaGetSymbolAddress((void**)&wl, g_wT_lo);

    cudaFuncSetAttribute(gemm_tc_kernel, cudaFuncAttributeMaxDynamicSharedMemorySize,
                         GEMM_SMEM);
    const int GEMM_GRID = (NN + 127) / 128;

    // launch order: index 3 = encoder GEMM (ncu capture slot)
    wprep_kernel<<<(4 * HID * HID + 255) / 256, 256>>>(W0, Wg, wh, wl);       // 0
    zero_deg_kernel<<<(NN + 255) / 256, 256>>>(deg);                          // 1
    count_deg_kernel<<<(ET + 255) / 256, 256>>>(ei, deg);                     // 2
    gemm_tc_kernel<<<GEMM_GRID, 512, GEMM_SMEM>>>(x, wh, wl, NN, 0,           // 3
                                                  b0, g0, be0, h, nullptr, nullptr);
    scan_part_kernel<<<NBLK, SCAN_BLK>>>(deg, bsum);                          // 4
    scan_top_kernel<<<1, 256>>>(bsum, off);                                   // 5
    scan_add_kernel<<<NBLK, SCAN_BLK>>>(deg, bsum, off, cur);                 // 6
    scatter_kernel<<<(ET + 255) / 256, 256>>>(ei, cur, csr);                  // 7

    for (int l = 0; l < LAYERS; l++) {
        gemm_tc_kernel<<<GEMM_GRID, 512, GEMM_SMEM>>>(
            h, wh + (l + 1) * HID * HID, wl + (l + 1) * HID * HID, NN, 1,
            att_src + l * 128, att_dst + l * 128, nullptr, tmp, as_, ad_);
        gat_aggregate_kernel<<<(NN * 32 + 255) / 256, 256>>>(
            tmp, as_, ad_, off, csr, bg + l * 128, gg + l * 128, bgg + l * 128, h);
    }

    pool_final_kernel<<<NB, 512>>>(h, batch, Wp, bp, gp, bep, out);
}